// round 14
// baseline (speedup 1.0000x reference)
#include <cuda_runtime.h>
#include <math.h>

#define BATCH 2
#define CH 4
#define HH 64
#define WW 64
#define LL (HH*WW)     // 4096
#define NHEADS 4
#define NB 128
#define NT 256
#define NNODE 16

struct Params {
    float kern[4][7];  // delay kernel table
    float pw[8];       // 0.8^i
};

// ---------------- scratch (device globals; no allocation allowed) ----------
__device__ float g_fb[2][BATCH][CH][HH][WW];
__device__ float4 g_qkv[BATCH][NHEADS][LL];  // (q, k*log2e, v, 0)
__device__ float g_attn[BATCH][NHEADS][LL];
__device__ float g_nodes[BATCH*NHEADS][NNODE];
// Monotonic per-block progress flag. NEVER reset: every launch publishes
// exactly 6 increments per block, so at entry each block's own flag == 6*L.
__device__ unsigned g_flag[NB];

__device__ __forceinline__ float sigm(float x) {
    return __fdividef(1.0f, 1.0f + __expf(-x));
}

__device__ __forceinline__ void wait_flag(const unsigned* p, unsigned tgt) {
    volatile const unsigned* vp = (volatile const unsigned*)p;
    while ((int)(*vp - tgt) < 0) __nanosleep(20);
}

// ---------------------------------------------------------------------------
__global__ void __launch_bounds__(NT, 1) fused_kernel(
    const float* __restrict__ x,
    const float* __restrict__ refl_w,
    const float* __restrict__ refl_d,
    const float* __restrict__ sc_w, const float* __restrict__ sc_b,
    const float* __restrict__ fb_w, const float* __restrict__ fb_b,
    const float* __restrict__ d1_w, const float* __restrict__ d1_b,
    const float* __restrict__ d2_w, const float* __restrict__ d2_b,
    const float* __restrict__ ipw, const float* __restrict__ ipb,
    const float* __restrict__ opw, const float* __restrict__ opb,
    const float* __restrict__ ocw, const float* __restrict__ ocb,
    float* __restrict__ out, Params par)
{
    __shared__ float  s_blur[CH][11][WW + 2];  // blurred rows y-5..y+5, col-padded
    __shared__ float  s_acc[CH][9][WW + 1];    // conv results / damped refl (padded)
    __shared__ float  s_fbc[CH][9][WW + 1];    // pre-i0 fb rows y-4..y+4 (per-thread slots)
    __shared__ float  s_w[CH * CH * 9];
    __shared__ float2 s_kv[LL];
    __shared__ float  s_q[NT];
    __shared__ float  s_nx[NNODE];
    __shared__ float  s_nR[NNODE];
    __shared__ float  s_red[32];
    __shared__ float  s_wgt[8];
    __shared__ int    s_kidx[8];
    __shared__ float  s_sp[2 * CH][WW];        // precomputed spatial conv (row y)
    __shared__ float  s_xc[CH][WW];            // x at (row y) for the dry mix
    __shared__ unsigned s_base;

    const int tid   = threadIdx.x;
    const int blk   = blockIdx.x;
    const int batch = blk >> 6;
    const int y     = blk & 63;
    const int c   = tid & 3;       // channel: 4 channels of a pixel in adjacent lanes
    const int col = tid >> 2;
    const int lane = tid & 31;

    if (tid == 0) s_base = *(volatile unsigned*)&g_flag[blk];  // 6*L
    if (tid < CH * CH * 9) s_w[tid] = fb_w[tid];
    if (tid < 88) {                // zero column padding of s_blur [c][rr][0|65]
        int cc = tid / 22, rem = tid % 22;
        s_blur[cc][rem >> 1][(rem & 1) * (WW + 1)] = 0.0f;
    }
    if (tid >= 96 && tid < 104) {
        int i = tid - 96;
        s_wgt[i] = sigm(__ldg(&refl_w[i])) * par.pw[i];
        int kidx = (int)floorf(__ldg(&refl_d[i]) * 0.5f);
        s_kidx[i] = min(max(kidx, 0), 3);
    }

    const float r_fbb  = __ldg(&fb_b[c]);
    float r_d1w[8], r_d1b2[2], r_d2w[8], r_d2b4[4];
    #pragma unroll
    for (int i = 0; i < 8; i++) { r_d1w[i] = __ldg(&d1_w[i]); r_d2w[i] = __ldg(&d2_w[i]); }
    r_d1b2[0] = __ldg(&d1_b[0]); r_d1b2[1] = __ldg(&d1_b[1]);
    #pragma unroll
    for (int i = 0; i < 4; i++) r_d2b4[i] = __ldg(&d2_b[i]);
    __syncthreads();

    const unsigned base = s_base;
    const float LOG2E = 1.4426950408889634f;
    const int lb = lane & ~3;

    float wet = 0.0f;
    float fb_self = 0.0f;

    // ============ reverb: 4 steps x 2 iterations (halo +-8, redundant) =====
    #pragma unroll 1
    for (int s = 0; s < 4; s++) {
        const int i0 = 2 * s, i1 = 2 * s + 1;
        const float* kr0 = par.kern[s_kidx[i0]];
        const float* kr1 = par.kern[s_kidx[i1]];
        const int rb = (s + 1) & 1;   // read buffer (s>0)
        const int wb = s & 1;         // write buffer (s<3)

        // ---- load fb rows y-8..y+8 (iter i0-1 state); stash center 9 ----
        {
            float f[17];
            if (s == 0) {
                #pragma unroll
                for (int r = 0; r < 17; r++) {
                    int yy = y - 8 + r;
                    f[r] = (yy >= 0 && yy < HH)
                         ? __ldg(&x[((batch * CH + c) * HH + yy) * WW + col]) * 0.1f : 0.0f;
                }
            } else {
                #pragma unroll
                for (int r = 0; r < 17; r++) {
                    if (r == 8) { f[8] = fb_self; continue; }
                    int yy = y - 8 + r;
                    f[r] = (yy >= 0 && yy < HH)
                         ? __ldcg(&g_fb[rb][batch][c][yy][col]) : 0.0f;
                }
            }
            // stash pre-i0 fb rows y-4..y+4 (private per-thread slot, no sync)
            #pragma unroll
            for (int k = 0; k < 9; k++) s_fbc[c][k][col] = f[k + 4];

            // ---- iter i0 blur: rows y-5..y+5 ----
            #pragma unroll
            for (int rr = 0; rr < 11; rr++) {
                float acc = 0.0f;
                #pragma unroll
                for (int t = 0; t < 7; t++)
                    acc = fmaf(kr0[t], f[rr + t], acc);
                int gy = y - 5 + rr;
                s_blur[c][rr][col + 1] = ((unsigned)gy < (unsigned)HH) ? acc : 0.0f;
            }
        }   // f[] dies here
        __syncthreads();

        // ---- iter i0 conv: pass 1, rows k=0..4 (blv[7], acc[5]) ----
        {
            float acc[5];
            #pragma unroll
            for (int k = 0; k < 5; k++) acc[k] = r_fbb;
            #pragma unroll
            for (int ci = 0; ci < CH; ci++)
                #pragma unroll
                for (int dx = 0; dx < 3; dx++) {
                    float blv[7];
                    #pragma unroll
                    for (int rr = 0; rr < 7; rr++)
                        blv[rr] = s_blur[ci][rr][col + dx];
                    #pragma unroll
                    for (int dy = 0; dy < 3; dy++) {
                        const float wv = s_w[(c * CH + ci) * 9 + dy * 3 + dx];
                        #pragma unroll
                        for (int k = 0; k < 5; k++)
                            acc[k] = fmaf(wv, blv[k + dy], acc[k]);
                    }
                }
            #pragma unroll
            for (int k = 0; k < 5; k++) s_acc[c][k][col] = acc[k];
        }
        // ---- iter i0 conv: pass 2, rows k=5..8 (blv[6], acc[4]) ----
        {
            float acc[4];
            #pragma unroll
            for (int k = 0; k < 4; k++) acc[k] = r_fbb;
            #pragma unroll
            for (int ci = 0; ci < CH; ci++)
                #pragma unroll
                for (int dx = 0; dx < 3; dx++) {
                    float blv[6];
                    #pragma unroll
                    for (int rr = 0; rr < 6; rr++)
                        blv[rr] = s_blur[ci][5 + rr][col + dx];
                    #pragma unroll
                    for (int dy = 0; dy < 3; dy++) {
                        const float wv = s_w[(c * CH + ci) * 9 + dy * 3 + dx];
                        #pragma unroll
                        for (int k = 0; k < 4; k++)
                            acc[k] = fmaf(wv, blv[k + dy], acc[k]);
                    }
                }
            #pragma unroll
            for (int k = 0; k < 4; k++) s_acc[c][5 + k][col] = acc[k];
        }
        __syncthreads();

        // ---- de-duplicated damp over 576 (row,col) ----
        #pragma unroll
        for (int p = tid; p < 576; p += NT) {
            const int kk = p >> 6;      // 0..8
            const int cl = p & 63;
            float a4[4];
            #pragma unroll
            for (int cc = 0; cc < 4; cc++) a4[cc] = s_acc[cc][kk][cl];
            float s1[2];
            #pragma unroll
            for (int j = 0; j < 2; j++) {
                float h1 = r_d1b2[j];
                #pragma unroll
                for (int cc = 0; cc < CH; cc++)
                    h1 = fmaf(r_d1w[j * CH + cc], a4[cc], h1);
                s1[j] = h1 * sigm(h1);
            }
            #pragma unroll
            for (int cc = 0; cc < 4; cc++) {
                float h2 = fmaf(r_d2w[cc * 2], s1[0],
                                fmaf(r_d2w[cc * 2 + 1], s1[1], r_d2b4[cc]));
                s_acc[cc][kk][cl] = a4[cc] * sigm(h2);
            }
        }
        __syncthreads();

        // ---- read back damped refl; build fb2 (iter i0 fb, rows y-4..y+4) --
        float fb2[9];
        #pragma unroll
        for (int k = 0; k < 9; k++) {
            float rd = s_acc[c][k][col];
            int gy = y - 4 + k;
            fb2[k] = ((unsigned)gy < (unsigned)HH)
                   ? fmaf(rd, 0.04f, s_fbc[c][k][col]) : 0.0f;
            if (k == 4) wet = fmaf(rd, s_wgt[i0], wet);
        }

        // ---- iter i1 blur: rows y-1..y+1 from fb2 ----
        #pragma unroll
        for (int rr = 0; rr < 3; rr++) {
            float acc = 0.0f;
            #pragma unroll
            for (int t = 0; t < 7; t++)
                acc = fmaf(kr1[t], fb2[rr + t], acc);
            int gy = y - 1 + rr;
            s_blur[c][rr][col + 1] = ((unsigned)gy < (unsigned)HH) ? acc : 0.0f;
        }
        __syncthreads();

        // ---- iter i1 conv at row y ----
        float r_out = r_fbb;
        #pragma unroll
        for (int ci = 0; ci < CH; ci++)
            #pragma unroll
            for (int dy = 0; dy < 3; dy++)
                #pragma unroll
                for (int dx = 0; dx < 3; dx++)
                    r_out = fmaf(s_w[(c * CH + ci) * 9 + dy * 3 + dx],
                                 s_blur[ci][dy][col + dx], r_out);

        // ---- iter i1 damp MLP at row y ----
        {
            float rf[4];
            #pragma unroll
            for (int j = 0; j < 4; j++)
                rf[j] = __shfl_sync(0xffffffffu, r_out, lb + j);
            float s1[2];
            #pragma unroll
            for (int j = 0; j < 2; j++) {
                float h1 = r_d1b2[j];
                #pragma unroll
                for (int cc = 0; cc < CH; cc++)
                    h1 = fmaf(r_d1w[j * CH + cc], rf[cc], h1);
                s1[j] = h1 * sigm(h1);
            }
            float h2 = fmaf(r_d2w[c * 2], s1[0], fmaf(r_d2w[c * 2 + 1], s1[1], r_d2b4[c]));
            float rd = r_out * sigm(h2);
            wet = fmaf(rd, s_wgt[i1], wet);
            fb_self = fmaf(rd, 0.04f, fb2[4]);
        }

        if (s < 3) {
            __stcg(&g_fb[wb][batch][c][y][col], fb_self);
            __syncthreads();                 // all block stores issued
            if (tid == 0) {
                __threadfence();             // publish fb row
                atomicExch(&g_flag[blk], base + (unsigned)(s + 1));
            }
            if (tid < 16) {
                int off = (tid < 8) ? (tid - 8) : (tid - 7);   // -8..-1, 1..8
                int ny = y + off;
                if (ny >= 0 && ny < HH)
                    wait_flag(&g_flag[blk + off], base + (unsigned)(s + 1));
            }
            __syncthreads();
        } else {
            // ---- QKV projection (head = lane channel), packed float4 store -
            float wf[4];
            #pragma unroll
            for (int k = 0; k < 4; k++)
                wf[k] = __shfl_sync(0xffffffffu, wet, lb + k);
            const int pix = y * WW + col;
            float qv = __ldg(&ipb[c]);
            float kv = __ldg(&ipb[4 + c]);
            float vv = __ldg(&ipb[8 + c]);
            #pragma unroll
            for (int cc = 0; cc < CH; cc++) {
                qv = fmaf(__ldg(&ipw[c * CH + cc]),       wf[cc], qv);
                kv = fmaf(__ldg(&ipw[(4 + c) * CH + cc]), wf[cc], kv);
                vv = fmaf(__ldg(&ipw[(8 + c) * CH + cc]), wf[cc], vv);
            }
            __stcg(&g_qkv[batch][c][pix], make_float4(qv, kv * LOG2E, vv, 0.0f));
            __syncthreads();
            if (tid == 0) {
                __threadfence();
                atomicExch(&g_flag[blk], base + 4u);   // qkv ready
            }
        }
    }

    // ---- overlap: precompute the x-only epilogue terms for row y ----------
    if (tid < 64) {
        const int px = tid;
        float xin[CH][9];
        #pragma unroll
        for (int ci = 0; ci < CH; ci++)
            #pragma unroll
            for (int dy = 0; dy < 3; dy++)
                #pragma unroll
                for (int dx = 0; dx < 3; dx++) {
                    int yy = y + dy - 1, xx = px + dx - 1;
                    float v = 0.0f;
                    if (yy >= 0 && yy < HH && xx >= 0 && xx < WW)
                        v = __ldg(&x[((batch * CH + ci) * HH + yy) * WW + xx]);
                    xin[ci][dy * 3 + dx] = v;
                }
        #pragma unroll
        for (int j = 0; j < 2 * CH; j++) {
            float a = __ldg(&sc_b[j]);
            #pragma unroll
            for (int ci = 0; ci < CH; ci++)
                #pragma unroll
                for (int kk = 0; kk < 9; kk++)
                    a = fmaf(__ldg(&sc_w[(j * CH + ci) * 9 + kk]), xin[ci][kk], a);
            s_sp[j][px] = a;
        }
        #pragma unroll
        for (int cc = 0; cc < CH; cc++) s_xc[cc][px] = xin[cc][4];
    }

    // ===================== attention: phase B (node eval) ==================
    const int bh    = blk >> 4;      // 0..7
    const int chunk = blk & 15;      // 0..15
    const int b     = batch;         // == bh >> 2
    const int h     = bh & 3;

    // wait for all 64 blocks of this batch to publish qkv (parallel poll)
    if (tid < 64) wait_flag(&g_flag[b * 64 + tid], base + 4u);
    __syncthreads();

    float kmx = -3.4e38f, kmn = 3.4e38f, qmx = -3.4e38f, qmn = 3.4e38f;
    #pragma unroll 4
    for (int i = 0; i < 16; i++) {
        int j = i * NT + tid;
        float4 t4 = __ldcg(&g_qkv[b][h][j]);
        s_kv[j] = make_float2(t4.y, t4.z);
        kmx = fmaxf(kmx, t4.y); kmn = fminf(kmn, t4.y);
        qmx = fmaxf(qmx, t4.x); qmn = fminf(qmn, t4.x);
        if (i == chunk) s_q[tid] = t4.x;
    }
    #pragma unroll
    for (int o = 16; o > 0; o >>= 1) {
        kmx = fmaxf(kmx, __shfl_xor_sync(0xffffffffu, kmx, o));
        kmn = fminf(kmn, __shfl_xor_sync(0xffffffffu, kmn, o));
        qmx = fmaxf(qmx, __shfl_xor_sync(0xffffffffu, qmx, o));
        qmn = fminf(qmn, __shfl_xor_sync(0xffffffffu, qmn, o));
    }
    const int wrp = tid >> 5;
    if (lane == 0) {
        s_red[wrp] = kmx; s_red[8 + wrp] = kmn;
        s_red[16 + wrp] = qmx; s_red[24 + wrp] = qmn;
    }
    __syncthreads();
    float ksmax = s_red[0], ksmin = s_red[8], qmax_ = s_red[16], qmin_ = s_red[24];
    #pragma unroll
    for (int i = 1; i < 8; i++) {
        ksmax = fmaxf(ksmax, s_red[i]);
        ksmin = fminf(ksmin, s_red[8 + i]);
        qmax_ = fmaxf(qmax_, s_red[16 + i]);
        qmin_ = fminf(qmin_, s_red[24 + i]);
    }

    const float dq = qmax_ - qmin_;
    const float dk = ksmax - ksmin;                 // log2 units
    const bool use_interp = (dq * dk <= 6.0f);      // guard for 16 nodes

    const float pad = 1e-4f * (fabsf(qmin_) + fabsf(qmax_)) + 1e-12f;
    const float a0 = qmin_ - pad, b0 = qmax_ + pad;
    const float cen = 0.5f * (a0 + b0), rad = 0.5f * (b0 - a0);
    if (tid < NNODE)
        s_nx[tid] = cen + rad * cosf((float)tid * (3.14159265358979323f / (NNODE - 1)));
    __syncthreads();

    if (use_interp) {
        // this block evaluates node == chunk with all 256 threads
        const float qt = s_nx[chunk];
        const float m2 = (qt >= 0.0f) ? qt * ksmax : qt * ksmin;
        float num = 0.0f, den = 0.0f;
        #pragma unroll 8
        for (int i = 0; i < LL / NT; i++) {
            float2 e2 = s_kv[i * NT + tid];
            float tt = fmaf(qt, e2.x, -m2);
            float e;
            asm("ex2.approx.f32 %0, %1;" : "=f"(e) : "f"(tt));
            den += e;
            num = fmaf(e, e2.y, num);
        }
        #pragma unroll
        for (int o = 16; o > 0; o >>= 1) {
            num += __shfl_xor_sync(0xffffffffu, num, o);
            den += __shfl_xor_sync(0xffffffffu, den, o);
        }
        if (lane == 0) { s_red[wrp] = num; s_red[8 + wrp] = den; }
        __syncthreads();
        if (tid == 0) {
            float N = 0.0f, D = 0.0f;
            #pragma unroll
            for (int w2 = 0; w2 < 8; w2++) { N += s_red[w2]; D += s_red[8 + w2]; }
            __stcg(&g_nodes[bh][chunk], N / D);
        }
    }
    __syncthreads();
    if (tid == 0) {
        __threadfence();
        atomicExch(&g_flag[blk], base + 5u);           // nodes ready
    }

    // ===================== attention: phase C (interpolate) ================
    if (tid < 16) wait_flag(&g_flag[bh * 16 + tid], base + 5u);
    __syncthreads();

    if (use_interp) {
        if (tid < NNODE) s_nR[tid] = __ldcg(&g_nodes[bh][tid]);
        __syncthreads();
        const float q = s_q[tid];
        float bn = 0.0f, bd = 0.0f;
        #pragma unroll
        for (int t2 = 0; t2 < NNODE; t2++) {
            float d = q - s_nx[t2];
            if (d == 0.0f) d = 1e-30f;
            float w = ((t2 == 0) || (t2 == NNODE - 1)) ? 0.5f : 1.0f;
            w = (t2 & 1) ? -w : w;
            float r = __fdividef(w, d);
            bn = fmaf(r, s_nR[t2], bn);
            bd += r;
        }
        __stcg(&g_attn[b][h][chunk * NT + tid], bn / bd);
    } else {
        const float qv = s_q[tid];
        const float m2 = (qv >= 0.0f) ? qv * ksmax : qv * ksmin;
        float num = 0.0f, den = 0.0f;
        #pragma unroll 8
        for (int j = 0; j < LL; j++) {
            float2 e2 = s_kv[j];
            float tt = fmaf(qv, e2.x, -m2);
            float e;
            asm("ex2.approx.f32 %0, %1;" : "=f"(e) : "f"(tt));
            den += e;
            num = fmaf(e, e2.y, num);
        }
        __stcg(&g_attn[b][h][chunk * NT + tid], num / den);
    }
    __syncthreads();
    if (tid == 0) {
        __threadfence();
        atomicExch(&g_flag[blk], base + 6u);           // attn ready
    }

    // =========================== epilogue: row y of this batch =============
    const int chunk_e = y >> 2;                        // (y*64)/256
    if (tid < 4)
        wait_flag(&g_flag[(batch * 4 + tid) * 16 + chunk_e], base + 6u);
    __syncthreads();

    if (tid < 64) {
        const int px  = tid;
        const int pix = y * WW + px;

        float o4[NHEADS];
        #pragma unroll
        for (int hh2 = 0; hh2 < NHEADS; hh2++) o4[hh2] = __ldcg(&g_attn[batch][hh2][pix]);
        float wet2[CH];
        #pragma unroll
        for (int cc = 0; cc < CH; cc++) {
            float a = __ldg(&opb[cc]);
            #pragma unroll
            for (int hh2 = 0; hh2 < NHEADS; hh2++)
                a = fmaf(__ldg(&opw[cc * CH + hh2]), o4[hh2], a);
            wet2[cc] = a;
        }

        #pragma unroll
        for (int cc = 0; cc < CH; cc++) {
            float a = __ldg(&ocb[cc]);
            #pragma unroll
            for (int j = 0; j < 2 * CH; j++)
                a = fmaf(__ldg(&ocw[cc * 12 + j]), s_sp[j][px], a);
            #pragma unroll
            for (int j = 0; j < CH; j++)
                a = fmaf(__ldg(&ocw[cc * 12 + 8 + j]), wet2[j], a);
            out[((batch * CH + cc) * HH + y) * WW + px] = 0.7f * s_xc[cc][px] + 0.3f * a;
        }
    }
}

// ---------------------------------------------------------------------------
extern "C" void kernel_launch(void* const* d_in, const int* in_sizes, int n_in,
                              void* d_out, int out_size)
{
    (void)in_sizes; (void)n_in; (void)out_size;
    const float* x      = (const float*)d_in[0];
    const float* refl_w = (const float*)d_in[1];
    const float* refl_d = (const float*)d_in[2];
    const float* sc_w   = (const float*)d_in[3];
    const float* sc_b   = (const float*)d_in[4];
    const float* fb_w   = (const float*)d_in[5];
    const float* fb_b   = (const float*)d_in[6];
    const float* d1_w   = (const float*)d_in[7];
    const float* d1_b   = (const float*)d_in[8];
    const float* d2_w   = (const float*)d_in[9];
    const float* d2_b   = (const float*)d_in[10];
    const float* ipw    = (const float*)d_in[11];
    const float* ipb    = (const float*)d_in[12];
    const float* opw    = (const float*)d_in[13];
    const float* opb    = (const float*)d_in[14];
    const float* oc_w   = (const float*)d_in[15];
    const float* oc_b   = (const float*)d_in[16];
    float* out = (float*)d_out;

    Params par;
    for (int r = 0; r < 4; r++)
        for (int c = 0; c < 7; c++) par.kern[r][c] = 0.0f;
    par.kern[0][3] = 1.0f;
    const int sizes[3] = {3, 5, 7};
    for (int ri = 0; ri < 3; ri++) {
        int ks = sizes[ri];
        double g[7], s = 0.0;
        for (int i = 0; i < ks; i++) {
            double xi = -2.0 + 4.0 * (double)i / (double)(ks - 1);
            g[i] = exp(-xi * xi);
            s += g[i];
        }
        int off = (7 - ks) / 2;
        for (int i = 0; i < ks; i++) par.kern[ri + 1][off + i] = (float)(g[i] / s);
    }
    for (int i = 0; i < 8; i++) par.pw[i] = (float)pow(0.8, (double)i);

    fused_kernel<<<NB, NT>>>(x, refl_w, refl_d, sc_w, sc_b, fb_w, fb_b,
                             d1_w, d1_b, d2_w, d2_b, ipw, ipb, opw, opb,
                             oc_w, oc_b, out, par);
}

// round 15
// speedup vs baseline: 1.0432x; 1.0432x over previous
#include <cuda_runtime.h>
#include <math.h>

#define BATCH 2
#define CH 4
#define HH 64
#define WW 64
#define LL (HH*WW)     // 4096
#define NHEADS 4
#define NB 128
#define NT 256
#define NNODE 16

struct Params {
    float kern[4][7];  // delay kernel table
    float pw[8];       // 0.8^i
};

// ---------------- scratch (device globals; no allocation allowed) ----------
__device__ float g_fb[2][BATCH][CH][HH][WW];
__device__ float4 g_qkv[BATCH][NHEADS][LL];  // (q, k*log2e, v, 0)
__device__ float g_attn[BATCH][NHEADS][LL];  // used only by exact fallback
__device__ float2 g_nodes[BATCH*NHEADS][NNODE];  // (node_x, node_R); x=NaN -> fallback
// Monotonic per-block progress flag. NEVER reset: every launch publishes
// exactly 5 increments per block, so at entry each block's own flag == 5*L.
__device__ unsigned g_flag[NB];

__device__ __forceinline__ float sigm(float x) {
    return __fdividef(1.0f, 1.0f + __expf(-x));
}

__device__ __forceinline__ void wait_flag(const unsigned* p, unsigned tgt) {
    volatile const unsigned* vp = (volatile const unsigned*)p;
    while ((int)(*vp - tgt) < 0) __nanosleep(20);
}

// ---------------------------------------------------------------------------
__global__ void __launch_bounds__(NT, 1) fused_kernel(
    const float* __restrict__ x,
    const float* __restrict__ refl_w,
    const float* __restrict__ refl_d,
    const float* __restrict__ sc_w, const float* __restrict__ sc_b,
    const float* __restrict__ fb_w, const float* __restrict__ fb_b,
    const float* __restrict__ d1_w, const float* __restrict__ d1_b,
    const float* __restrict__ d2_w, const float* __restrict__ d2_b,
    const float* __restrict__ ipw, const float* __restrict__ ipb,
    const float* __restrict__ opw, const float* __restrict__ opb,
    const float* __restrict__ ocw, const float* __restrict__ ocb,
    float* __restrict__ out, Params par)
{
    __shared__ float  s_blur[CH][11][WW + 2];  // blurred rows y-5..y+5, col-padded
    __shared__ float  s_acc[CH][9][WW + 1];    // conv results / damped refl (padded)
    __shared__ float  s_w[CH * CH * 9];
    __shared__ float2 s_kv[LL];
    __shared__ float  s_q[NT];
    __shared__ float  s_nx[NNODE];
    __shared__ float2 s_n4[NHEADS][NNODE];     // epilogue: nodes of all 4 heads
    __shared__ float  s_red[32];
    __shared__ float  s_wgt[8];
    __shared__ int    s_kidx[8];
    __shared__ float  s_sp[2 * CH][WW];        // precomputed spatial conv (row y)
    __shared__ float  s_xc[CH][WW];            // x at (row y) for the dry mix
    __shared__ unsigned s_base;

    const int tid   = threadIdx.x;
    const int blk   = blockIdx.x;
    const int batch = blk >> 6;
    const int y     = blk & 63;
    const int c   = tid & 3;       // channel: 4 channels of a pixel in adjacent lanes
    const int col = tid >> 2;
    const int lane = tid & 31;

    if (tid == 0) s_base = *(volatile unsigned*)&g_flag[blk];  // 5*L
    if (tid < CH * CH * 9) s_w[tid] = fb_w[tid];
    if (tid < 88) {                // zero column padding of s_blur [c][rr][0|65]
        int cc = tid / 22, rem = tid % 22;
        s_blur[cc][rem >> 1][(rem & 1) * (WW + 1)] = 0.0f;
    }
    if (tid >= 96 && tid < 104) {
        int i = tid - 96;
        s_wgt[i] = sigm(__ldg(&refl_w[i])) * par.pw[i];
        int kidx = (int)floorf(__ldg(&refl_d[i]) * 0.5f);
        s_kidx[i] = min(max(kidx, 0), 3);
    }

    const float r_fbb  = __ldg(&fb_b[c]);
    float r_d1w[8], r_d1b2[2], r_d2w[8], r_d2b4[4];
    #pragma unroll
    for (int i = 0; i < 8; i++) { r_d1w[i] = __ldg(&d1_w[i]); r_d2w[i] = __ldg(&d2_w[i]); }
    r_d1b2[0] = __ldg(&d1_b[0]); r_d1b2[1] = __ldg(&d1_b[1]);
    #pragma unroll
    for (int i = 0; i < 4; i++) r_d2b4[i] = __ldg(&d2_b[i]);
    __syncthreads();

    const unsigned base = s_base;
    const float LOG2E = 1.4426950408889634f;
    const int lb = lane & ~3;

    float wet = 0.0f;
    float fb_self = 0.0f;

    // ============ reverb: 4 steps x 2 iterations (halo +-8, redundant) =====
    #pragma unroll 1
    for (int s = 0; s < 4; s++) {
        const int i0 = 2 * s, i1 = 2 * s + 1;
        const float* kr0 = par.kern[s_kidx[i0]];
        const float* kr1 = par.kern[s_kidx[i1]];
        const int rb = (s + 1) & 1;   // read buffer (s>0)
        const int wb = s & 1;         // write buffer (s<3)

        // ---- load fb rows y-8..y+8 (iter i0-1 state) ----
        float f[17];
        if (s == 0) {
            #pragma unroll
            for (int r = 0; r < 17; r++) {
                int yy = y - 8 + r;
                f[r] = (yy >= 0 && yy < HH)
                     ? __ldg(&x[((batch * CH + c) * HH + yy) * WW + col]) * 0.1f : 0.0f;
            }
        } else {
            #pragma unroll
            for (int r = 0; r < 17; r++) {
                if (r == 8) { f[8] = fb_self; continue; }
                int yy = y - 8 + r;
                f[r] = (yy >= 0 && yy < HH)
                     ? __ldcg(&g_fb[rb][batch][c][yy][col]) : 0.0f;
            }
        }

        // ---- iter i0 blur: rows y-5..y+5 ----
        #pragma unroll
        for (int rr = 0; rr < 11; rr++) {
            float acc = 0.0f;
            #pragma unroll
            for (int t = 0; t < 7; t++)
                acc = fmaf(kr0[t], f[rr + t], acc);
            int gy = y - 5 + rr;
            s_blur[c][rr][col + 1] = ((unsigned)gy < (unsigned)HH) ? acc : 0.0f;
        }
        __syncthreads();

        // ---- iter i0 conv: 9 rows (y-4..y+4), register-blocked reads ----
        float acc9[9];
        #pragma unroll
        for (int k = 0; k < 9; k++) acc9[k] = r_fbb;
        #pragma unroll
        for (int ci = 0; ci < CH; ci++)
            #pragma unroll
            for (int dx = 0; dx < 3; dx++) {
                float blv[11];
                #pragma unroll
                for (int rr = 0; rr < 11; rr++)
                    blv[rr] = s_blur[ci][rr][col + dx];
                #pragma unroll
                for (int dy = 0; dy < 3; dy++) {
                    const float wv = s_w[(c * CH + ci) * 9 + dy * 3 + dx];
                    #pragma unroll
                    for (int k = 0; k < 9; k++)
                        acc9[k] = fmaf(wv, blv[k + dy], acc9[k]);
                }
            }

        // ---- stash conv results; de-duplicated damp over 576 (row,col) ----
        #pragma unroll
        for (int k = 0; k < 9; k++) s_acc[c][k][col] = acc9[k];
        __syncthreads();

        #pragma unroll
        for (int p = tid; p < 576; p += NT) {
            const int kk = p >> 6;      // 0..8
            const int cl = p & 63;
            float a4[4];
            #pragma unroll
            for (int cc = 0; cc < 4; cc++) a4[cc] = s_acc[cc][kk][cl];
            float s1[2];
            #pragma unroll
            for (int j = 0; j < 2; j++) {
                float h1 = r_d1b2[j];
                #pragma unroll
                for (int cc = 0; cc < CH; cc++)
                    h1 = fmaf(r_d1w[j * CH + cc], a4[cc], h1);
                s1[j] = h1 * sigm(h1);
            }
            #pragma unroll
            for (int cc = 0; cc < 4; cc++) {
                float h2 = fmaf(r_d2w[cc * 2], s1[0],
                                fmaf(r_d2w[cc * 2 + 1], s1[1], r_d2b4[cc]));
                s_acc[cc][kk][cl] = a4[cc] * sigm(h2);
            }
        }
        __syncthreads();

        // ---- read back damped refl; build fb2 (iter i0 fb, rows y-4..y+4) --
        float fb2[9];
        #pragma unroll
        for (int k = 0; k < 9; k++) {
            float rd = s_acc[c][k][col];
            int gy = y - 4 + k;
            fb2[k] = ((unsigned)gy < (unsigned)HH) ? fmaf(rd, 0.04f, f[k + 4]) : 0.0f;
            if (k == 4) wet = fmaf(rd, s_wgt[i0], wet);
        }

        // ---- iter i1 blur: rows y-1..y+1 from fb2 ----
        #pragma unroll
        for (int rr = 0; rr < 3; rr++) {
            float acc = 0.0f;
            #pragma unroll
            for (int t = 0; t < 7; t++)
                acc = fmaf(kr1[t], fb2[rr + t], acc);
            int gy = y - 1 + rr;
            s_blur[c][rr][col + 1] = ((unsigned)gy < (unsigned)HH) ? acc : 0.0f;
        }
        __syncthreads();

        // ---- iter i1 conv at row y ----
        float r_out = r_fbb;
        #pragma unroll
        for (int ci = 0; ci < CH; ci++)
            #pragma unroll
            for (int dy = 0; dy < 3; dy++)
                #pragma unroll
                for (int dx = 0; dx < 3; dx++)
                    r_out = fmaf(s_w[(c * CH + ci) * 9 + dy * 3 + dx],
                                 s_blur[ci][dy][col + dx], r_out);

        // ---- iter i1 damp MLP at row y ----
        {
            float rf[4];
            #pragma unroll
            for (int j = 0; j < 4; j++)
                rf[j] = __shfl_sync(0xffffffffu, r_out, lb + j);
            float s1[2];
            #pragma unroll
            for (int j = 0; j < 2; j++) {
                float h1 = r_d1b2[j];
                #pragma unroll
                for (int cc = 0; cc < CH; cc++)
                    h1 = fmaf(r_d1w[j * CH + cc], rf[cc], h1);
                s1[j] = h1 * sigm(h1);
            }
            float h2 = fmaf(r_d2w[c * 2], s1[0], fmaf(r_d2w[c * 2 + 1], s1[1], r_d2b4[c]));
            float rd = r_out * sigm(h2);
            wet = fmaf(rd, s_wgt[i1], wet);
            fb_self = fmaf(rd, 0.04f, fb2[4]);
        }

        if (s < 3) {
            __stcg(&g_fb[wb][batch][c][y][col], fb_self);
            __syncthreads();                 // all block stores issued
            if (tid == 0) {
                __threadfence();             // publish fb row
                atomicExch(&g_flag[blk], base + (unsigned)(s + 1));
            }
            if (tid < 16) {
                int off = (tid < 8) ? (tid - 8) : (tid - 7);   // -8..-1, 1..8
                int ny = y + off;
                if (ny >= 0 && ny < HH)
                    wait_flag(&g_flag[blk + off], base + (unsigned)(s + 1));
            }
            __syncthreads();
        } else {
            // ---- QKV projection (head = lane channel), packed float4 store -
            float wf[4];
            #pragma unroll
            for (int k = 0; k < 4; k++)
                wf[k] = __shfl_sync(0xffffffffu, wet, lb + k);
            const int pix = y * WW + col;
            float qv = __ldg(&ipb[c]);
            float kv = __ldg(&ipb[4 + c]);
            float vv = __ldg(&ipb[8 + c]);
            #pragma unroll
            for (int cc = 0; cc < CH; cc++) {
                qv = fmaf(__ldg(&ipw[c * CH + cc]),       wf[cc], qv);
                kv = fmaf(__ldg(&ipw[(4 + c) * CH + cc]), wf[cc], kv);
                vv = fmaf(__ldg(&ipw[(8 + c) * CH + cc]), wf[cc], vv);
            }
            __stcg(&g_qkv[batch][c][pix], make_float4(qv, kv * LOG2E, vv, 0.0f));
            __syncthreads();
            if (tid == 0) {
                __threadfence();
                atomicExch(&g_flag[blk], base + 4u);   // qkv ready
            }
        }
    }

    // ---- overlap: precompute the x-only epilogue terms for row y ----------
    if (tid < 64) {
        const int px = tid;
        float xin[CH][9];
        #pragma unroll
        for (int ci = 0; ci < CH; ci++)
            #pragma unroll
            for (int dy = 0; dy < 3; dy++)
                #pragma unroll
                for (int dx = 0; dx < 3; dx++) {
                    int yy = y + dy - 1, xx = px + dx - 1;
                    float v = 0.0f;
                    if (yy >= 0 && yy < HH && xx >= 0 && xx < WW)
                        v = __ldg(&x[((batch * CH + ci) * HH + yy) * WW + xx]);
                    xin[ci][dy * 3 + dx] = v;
                }
        #pragma unroll
        for (int j = 0; j < 2 * CH; j++) {
            float a = __ldg(&sc_b[j]);
            #pragma unroll
            for (int ci = 0; ci < CH; ci++)
                #pragma unroll
                for (int kk = 0; kk < 9; kk++)
                    a = fmaf(__ldg(&sc_w[(j * CH + ci) * 9 + kk]), xin[ci][kk], a);
            s_sp[j][px] = a;
        }
        #pragma unroll
        for (int cc = 0; cc < CH; cc++) s_xc[cc][px] = xin[cc][4];
    }

    // ===================== attention: node eval (one node per block) =======
    const int bh    = blk >> 4;      // 0..7
    const int chunk = blk & 15;      // 0..15
    const int b     = batch;         // == bh >> 2
    const int h     = bh & 3;

    // wait for all 64 blocks of this batch to publish qkv (parallel poll)
    if (tid < 64) wait_flag(&g_flag[b * 64 + tid], base + 4u);
    __syncthreads();

    float kmx = -3.4e38f, kmn = 3.4e38f, qmx = -3.4e38f, qmn = 3.4e38f;
    #pragma unroll 4
    for (int i = 0; i < 16; i++) {
        int j = i * NT + tid;
        float4 t4 = __ldcg(&g_qkv[b][h][j]);
        s_kv[j] = make_float2(t4.y, t4.z);
        kmx = fmaxf(kmx, t4.y); kmn = fminf(kmn, t4.y);
        qmx = fmaxf(qmx, t4.x); qmn = fminf(qmn, t4.x);
        if (i == chunk) s_q[tid] = t4.x;
    }
    #pragma unroll
    for (int o = 16; o > 0; o >>= 1) {
        kmx = fmaxf(kmx, __shfl_xor_sync(0xffffffffu, kmx, o));
        kmn = fminf(kmn, __shfl_xor_sync(0xffffffffu, kmn, o));
        qmx = fmaxf(qmx, __shfl_xor_sync(0xffffffffu, qmx, o));
        qmn = fminf(qmn, __shfl_xor_sync(0xffffffffu, qmn, o));
    }
    const int wrp = tid >> 5;
    if (lane == 0) {
        s_red[wrp] = kmx; s_red[8 + wrp] = kmn;
        s_red[16 + wrp] = qmx; s_red[24 + wrp] = qmn;
    }
    __syncthreads();
    float ksmax = s_red[0], ksmin = s_red[8], qmax_ = s_red[16], qmin_ = s_red[24];
    #pragma unroll
    for (int i = 1; i < 8; i++) {
        ksmax = fmaxf(ksmax, s_red[i]);
        ksmin = fminf(ksmin, s_red[8 + i]);
        qmax_ = fmaxf(qmax_, s_red[16 + i]);
        qmin_ = fminf(qmin_, s_red[24 + i]);
    }

    const float dq = qmax_ - qmin_;
    const float dk = ksmax - ksmin;                 // log2 units
    const bool use_interp = (dq * dk <= 6.0f);      // guard for 16 nodes

    const float pad = 1e-4f * (fabsf(qmin_) + fabsf(qmax_)) + 1e-12f;
    const float a0 = qmin_ - pad, b0 = qmax_ + pad;
    const float cen = 0.5f * (a0 + b0), rad = 0.5f * (b0 - a0);
    if (tid < NNODE)
        s_nx[tid] = cen + rad * cosf((float)tid * (3.14159265358979323f / (NNODE - 1)));
    __syncthreads();

    if (use_interp) {
        // this block evaluates node == chunk with all 256 threads
        const float qt = s_nx[chunk];
        const float m2 = (qt >= 0.0f) ? qt * ksmax : qt * ksmin;
        float num = 0.0f, den = 0.0f;
        #pragma unroll 8
        for (int i = 0; i < LL / NT; i++) {
            float2 e2 = s_kv[i * NT + tid];
            float tt = fmaf(qt, e2.x, -m2);
            float e;
            asm("ex2.approx.f32 %0, %1;" : "=f"(e) : "f"(tt));
            den += e;
            num = fmaf(e, e2.y, num);
        }
        #pragma unroll
        for (int o = 16; o > 0; o >>= 1) {
            num += __shfl_xor_sync(0xffffffffu, num, o);
            den += __shfl_xor_sync(0xffffffffu, den, o);
        }
        if (lane == 0) { s_red[wrp] = num; s_red[8 + wrp] = den; }
        __syncthreads();
        if (tid == 0) {
            float N = 0.0f, D = 0.0f;
            #pragma unroll
            for (int w2 = 0; w2 < 8; w2++) { N += s_red[w2]; D += s_red[8 + w2]; }
            __stcg(&g_nodes[bh][chunk], make_float2(qt, N / D));
        }
    } else {
        // exact fallback: compute this chunk's 256 queries here in phase B
        const float qv = s_q[tid];
        const float m2 = (qv >= 0.0f) ? qv * ksmax : qv * ksmin;
        float num = 0.0f, den = 0.0f;
        #pragma unroll 8
        for (int j = 0; j < LL; j++) {
            float2 e2 = s_kv[j];
            float tt = fmaf(qv, e2.x, -m2);
            float e;
            asm("ex2.approx.f32 %0, %1;" : "=f"(e) : "f"(tt));
            den += e;
            num = fmaf(e, e2.y, num);
        }
        __stcg(&g_attn[b][h][chunk * NT + tid], num / den);
        if (tid == 0)   // NaN sentinel: epilogue reads g_attn instead
            __stcg(&g_nodes[bh][chunk], make_float2(__int_as_float(0x7fc00000), 0.0f));
    }
    __syncthreads();
    if (tid == 0) {
        __threadfence();
        atomicExch(&g_flag[blk], base + 5u);           // nodes/attn ready
    }

    // ============== epilogue: interpolate + mix, row y of this batch =======
    // needs nodes (or fallback attn) of ALL 4 heads of this batch -> all 64
    // blocks of the batch at flag 5 (parallel poll).
    if (tid < 64) wait_flag(&g_flag[batch * 64 + tid], base + 5u);
    __syncthreads();

    if (tid < 64) s_n4[tid >> 4][tid & 15] = __ldcg(&g_nodes[batch * 4 + (tid >> 4)][tid & 15]);
    __syncthreads();

    if (tid < 64) {
        const int px  = tid;
        const int pix = y * WW + px;

        float o4[NHEADS];
        #pragma unroll
        for (int hh2 = 0; hh2 < NHEADS; hh2++) {
            if (isnan(s_n4[hh2][0].x)) {
                o4[hh2] = __ldcg(&g_attn[batch][hh2][pix]);
            } else {
                const float q = __ldcg(&g_qkv[batch][hh2][pix]).x;
                float bn = 0.0f, bd = 0.0f;
                #pragma unroll
                for (int t2 = 0; t2 < NNODE; t2++) {
                    float2 nd = s_n4[hh2][t2];
                    float d = q - nd.x;
                    if (d == 0.0f) d = 1e-30f;
                    float w = ((t2 == 0) || (t2 == NNODE - 1)) ? 0.5f : 1.0f;
                    w = (t2 & 1) ? -w : w;
                    float r = __fdividef(w, d);
                    bn = fmaf(r, nd.y, bn);
                    bd += r;
                }
                o4[hh2] = bn / bd;
            }
        }

        float wet2[CH];
        #pragma unroll
        for (int cc = 0; cc < CH; cc++) {
            float a = __ldg(&opb[cc]);
            #pragma unroll
            for (int hh2 = 0; hh2 < NHEADS; hh2++)
                a = fmaf(__ldg(&opw[cc * CH + hh2]), o4[hh2], a);
            wet2[cc] = a;
        }

        #pragma unroll
        for (int cc = 0; cc < CH; cc++) {
            float a = __ldg(&ocb[cc]);
            #pragma unroll
            for (int j = 0; j < 2 * CH; j++)
                a = fmaf(__ldg(&ocw[cc * 12 + j]), s_sp[j][px], a);
            #pragma unroll
            for (int j = 0; j < CH; j++)
                a = fmaf(__ldg(&ocw[cc * 12 + 8 + j]), wet2[j], a);
            out[((batch * CH + cc) * HH + y) * WW + px] = 0.7f * s_xc[cc][px] + 0.3f * a;
        }
    }
}

// ---------------------------------------------------------------------------
extern "C" void kernel_launch(void* const* d_in, const int* in_sizes, int n_in,
                              void* d_out, int out_size)
{
    (void)in_sizes; (void)n_in; (void)out_size;
    const float* x      = (const float*)d_in[0];
    const float* refl_w = (const float*)d_in[1];
    const float* refl_d = (const float*)d_in[2];
    const float* sc_w   = (const float*)d_in[3];
    const float* sc_b   = (const float*)d_in[4];
    const float* fb_w   = (const float*)d_in[5];
    const float* fb_b   = (const float*)d_in[6];
    const float* d1_w   = (const float*)d_in[7];
    const float* d1_b   = (const float*)d_in[8];
    const float* d2_w   = (const float*)d_in[9];
    const float* d2_b   = (const float*)d_in[10];
    const float* ipw    = (const float*)d_in[11];
    const float* ipb    = (const float*)d_in[12];
    const float* opw    = (const float*)d_in[13];
    const float* opb    = (const float*)d_in[14];
    const float* oc_w   = (const float*)d_in[15];
    const float* oc_b   = (const float*)d_in[16];
    float* out = (float*)d_out;

    Params par;
    for (int r = 0; r < 4; r++)
        for (int c = 0; c < 7; c++) par.kern[r][c] = 0.0f;
    par.kern[0][3] = 1.0f;
    const int sizes[3] = {3, 5, 7};
    for (int ri = 0; ri < 3; ri++) {
        int ks = sizes[ri];
        double g[7], s = 0.0;
        for (int i = 0; i < ks; i++) {
            double xi = -2.0 + 4.0 * (double)i / (double)(ks - 1);
            g[i] = exp(-xi * xi);
            s += g[i];
        }
        int off = (7 - ks) / 2;
        for (int i = 0; i < ks; i++) par.kern[ri + 1][off + i] = (float)(g[i] / s);
    }
    for (int i = 0; i < 8; i++) par.pw[i] = (float)pow(0.8, (double)i);

    fused_kernel<<<NB, NT>>>(x, refl_w, refl_d, sc_w, sc_b, fb_w, fb_b,
                             d1_w, d1_b, d2_w, d2_b, ipw, ipb, opw, opb,
                             oc_w, oc_b, out, par);
}

// round 16
// speedup vs baseline: 1.1376x; 1.0904x over previous
#include <cuda_runtime.h>
#include <math.h>

#define BATCH 2
#define CH 4
#define HH 64
#define WW 64
#define LL (HH*WW)     // 4096
#define NHEADS 4
#define NB 128
#define NT 256
#define NNODE 16

struct Params {
    float kern[4][7];  // delay kernel table
    float pw[8];       // 0.8^i
};

// ---------------- scratch (device globals; no allocation allowed) ----------
__device__ float g_fb[2][BATCH][CH][HH][WW];
__device__ float4 g_qkv[BATCH][NHEADS][LL];  // (q, k*log2e, v, 0)
__device__ float g_attn[BATCH][NHEADS][LL];
__device__ float g_nodes[BATCH*NHEADS][NNODE];
// Monotonic per-block progress flag. NEVER reset: every launch publishes
// exactly 6 increments per block, so at entry each block's own flag == 6*L.
__device__ unsigned g_flag[NB];

__device__ __forceinline__ float sigm(float x) {
    return __fdividef(1.0f, 1.0f + __expf(-x));
}

__device__ __forceinline__ void wait_flag(const unsigned* p, unsigned tgt) {
    volatile const unsigned* vp = (volatile const unsigned*)p;
    while ((int)(*vp - tgt) < 0) __nanosleep(20);
}

// ---------------------------------------------------------------------------
__global__ void __launch_bounds__(NT, 1) fused_kernel(
    const float* __restrict__ x,
    const float* __restrict__ refl_w,
    const float* __restrict__ refl_d,
    const float* __restrict__ sc_w, const float* __restrict__ sc_b,
    const float* __restrict__ fb_w, const float* __restrict__ fb_b,
    const float* __restrict__ d1_w, const float* __restrict__ d1_b,
    const float* __restrict__ d2_w, const float* __restrict__ d2_b,
    const float* __restrict__ ipw, const float* __restrict__ ipb,
    const float* __restrict__ opw, const float* __restrict__ opb,
    const float* __restrict__ ocw, const float* __restrict__ ocb,
    float* __restrict__ out, Params par)
{
    __shared__ float  s_blur[CH][11][WW + 2];  // blurred rows y-5..y+5, col-padded
    __shared__ float  s_acc[CH][9][WW + 1];    // conv results / damped refl (padded)
    __shared__ float  s_w[CH * CH * 9];
    __shared__ float2 s_kv[LL];                // used only by exact fallback
    __shared__ float  s_q[NT];
    __shared__ float  s_nx[NNODE];
    __shared__ float  s_nR[NNODE];
    __shared__ float  s_red[32];
    __shared__ float  s_wgt[8];
    __shared__ int    s_kidx[8];
    __shared__ float  s_sp[2 * CH][WW];        // precomputed spatial conv (row y)
    __shared__ float  s_xc[CH][WW];            // x at (row y) for the dry mix
    __shared__ unsigned s_base;

    const int tid   = threadIdx.x;
    const int blk   = blockIdx.x;
    const int batch = blk >> 6;
    const int y     = blk & 63;
    const int c   = tid & 3;       // channel: 4 channels of a pixel in adjacent lanes
    const int col = tid >> 2;
    const int lane = tid & 31;

    if (tid == 0) s_base = *(volatile unsigned*)&g_flag[blk];  // 6*L
    if (tid < CH * CH * 9) s_w[tid] = fb_w[tid];
    if (tid < 88) {                // zero column padding of s_blur [c][rr][0|65]
        int cc = tid / 22, rem = tid % 22;
        s_blur[cc][rem >> 1][(rem & 1) * (WW + 1)] = 0.0f;
    }
    if (tid >= 96 && tid < 104) {
        int i = tid - 96;
        s_wgt[i] = sigm(__ldg(&refl_w[i])) * par.pw[i];
        int kidx = (int)floorf(__ldg(&refl_d[i]) * 0.5f);
        s_kidx[i] = min(max(kidx, 0), 3);
    }

    const float r_fbb  = __ldg(&fb_b[c]);
    float r_d1w[8], r_d1b2[2], r_d2w[8], r_d2b4[4];
    #pragma unroll
    for (int i = 0; i < 8; i++) { r_d1w[i] = __ldg(&d1_w[i]); r_d2w[i] = __ldg(&d2_w[i]); }
    r_d1b2[0] = __ldg(&d1_b[0]); r_d1b2[1] = __ldg(&d1_b[1]);
    #pragma unroll
    for (int i = 0; i < 4; i++) r_d2b4[i] = __ldg(&d2_b[i]);
    __syncthreads();

    const unsigned base = s_base;
    const float LOG2E = 1.4426950408889634f;
    const int lb = lane & ~3;

    float wet = 0.0f;
    float fb_self = 0.0f;

    // ============ reverb: 4 steps x 2 iterations (halo +-8, redundant) =====
    #pragma unroll 1
    for (int s = 0; s < 4; s++) {
        const int i0 = 2 * s, i1 = 2 * s + 1;
        const float* kr0 = par.kern[s_kidx[i0]];
        const float* kr1 = par.kern[s_kidx[i1]];
        const int rb = (s + 1) & 1;   // read buffer (s>0)
        const int wb = s & 1;         // write buffer (s<3)

        // ---- load fb rows y-8..y+8 (iter i0-1 state) ----
        float f[17];
        if (s == 0) {
            #pragma unroll
            for (int r = 0; r < 17; r++) {
                int yy = y - 8 + r;
                f[r] = (yy >= 0 && yy < HH)
                     ? __ldg(&x[((batch * CH + c) * HH + yy) * WW + col]) * 0.1f : 0.0f;
            }
        } else {
            #pragma unroll
            for (int r = 0; r < 17; r++) {
                if (r == 8) { f[8] = fb_self; continue; }
                int yy = y - 8 + r;
                f[r] = (yy >= 0 && yy < HH)
                     ? __ldcg(&g_fb[rb][batch][c][yy][col]) : 0.0f;
            }
        }

        // ---- iter i0 blur: rows y-5..y+5 ----
        #pragma unroll
        for (int rr = 0; rr < 11; rr++) {
            float acc = 0.0f;
            #pragma unroll
            for (int t = 0; t < 7; t++)
                acc = fmaf(kr0[t], f[rr + t], acc);
            int gy = y - 5 + rr;
            s_blur[c][rr][col + 1] = ((unsigned)gy < (unsigned)HH) ? acc : 0.0f;
        }
        __syncthreads();

        // ---- iter i0 conv: 9 rows (y-4..y+4), register-blocked reads ----
        float acc9[9];
        #pragma unroll
        for (int k = 0; k < 9; k++) acc9[k] = r_fbb;
        #pragma unroll
        for (int ci = 0; ci < CH; ci++)
            #pragma unroll
            for (int dx = 0; dx < 3; dx++) {
                float blv[11];
                #pragma unroll
                for (int rr = 0; rr < 11; rr++)
                    blv[rr] = s_blur[ci][rr][col + dx];
                #pragma unroll
                for (int dy = 0; dy < 3; dy++) {
                    const float wv = s_w[(c * CH + ci) * 9 + dy * 3 + dx];
                    #pragma unroll
                    for (int k = 0; k < 9; k++)
                        acc9[k] = fmaf(wv, blv[k + dy], acc9[k]);
                }
            }

        // ---- stash conv results; de-duplicated damp over 576 (row,col) ----
        #pragma unroll
        for (int k = 0; k < 9; k++) s_acc[c][k][col] = acc9[k];
        __syncthreads();

        #pragma unroll
        for (int p = tid; p < 576; p += NT) {
            const int kk = p >> 6;      // 0..8
            const int cl = p & 63;
            float a4[4];
            #pragma unroll
            for (int cc = 0; cc < 4; cc++) a4[cc] = s_acc[cc][kk][cl];
            float s1[2];
            #pragma unroll
            for (int j = 0; j < 2; j++) {
                float h1 = r_d1b2[j];
                #pragma unroll
                for (int cc = 0; cc < CH; cc++)
                    h1 = fmaf(r_d1w[j * CH + cc], a4[cc], h1);
                s1[j] = h1 * sigm(h1);
            }
            #pragma unroll
            for (int cc = 0; cc < 4; cc++) {
                float h2 = fmaf(r_d2w[cc * 2], s1[0],
                                fmaf(r_d2w[cc * 2 + 1], s1[1], r_d2b4[cc]));
                s_acc[cc][kk][cl] = a4[cc] * sigm(h2);
            }
        }
        __syncthreads();

        // ---- read back damped refl; build fb2 (iter i0 fb, rows y-4..y+4) --
        float fb2[9];
        #pragma unroll
        for (int k = 0; k < 9; k++) {
            float rd = s_acc[c][k][col];
            int gy = y - 4 + k;
            fb2[k] = ((unsigned)gy < (unsigned)HH) ? fmaf(rd, 0.04f, f[k + 4]) : 0.0f;
            if (k == 4) wet = fmaf(rd, s_wgt[i0], wet);
        }

        // ---- iter i1 blur: rows y-1..y+1 from fb2 ----
        #pragma unroll
        for (int rr = 0; rr < 3; rr++) {
            float acc = 0.0f;
            #pragma unroll
            for (int t = 0; t < 7; t++)
                acc = fmaf(kr1[t], fb2[rr + t], acc);
            int gy = y - 1 + rr;
            s_blur[c][rr][col + 1] = ((unsigned)gy < (unsigned)HH) ? acc : 0.0f;
        }
        __syncthreads();

        // ---- iter i1 conv at row y ----
        float r_out = r_fbb;
        #pragma unroll
        for (int ci = 0; ci < CH; ci++)
            #pragma unroll
            for (int dy = 0; dy < 3; dy++)
                #pragma unroll
                for (int dx = 0; dx < 3; dx++)
                    r_out = fmaf(s_w[(c * CH + ci) * 9 + dy * 3 + dx],
                                 s_blur[ci][dy][col + dx], r_out);

        // ---- iter i1 damp MLP at row y ----
        {
            float rf[4];
            #pragma unroll
            for (int j = 0; j < 4; j++)
                rf[j] = __shfl_sync(0xffffffffu, r_out, lb + j);
            float s1[2];
            #pragma unroll
            for (int j = 0; j < 2; j++) {
                float h1 = r_d1b2[j];
                #pragma unroll
                for (int cc = 0; cc < CH; cc++)
                    h1 = fmaf(r_d1w[j * CH + cc], rf[cc], h1);
                s1[j] = h1 * sigm(h1);
            }
            float h2 = fmaf(r_d2w[c * 2], s1[0], fmaf(r_d2w[c * 2 + 1], s1[1], r_d2b4[c]));
            float rd = r_out * sigm(h2);
            wet = fmaf(rd, s_wgt[i1], wet);
            fb_self = fmaf(rd, 0.04f, fb2[4]);
        }

        if (s < 3) {
            __stcg(&g_fb[wb][batch][c][y][col], fb_self);
            __syncthreads();                 // all block stores issued
            if (tid == 0) {
                __threadfence();             // publish fb row
                atomicExch(&g_flag[blk], base + (unsigned)(s + 1));
            }
            if (tid < 16) {
                int off = (tid < 8) ? (tid - 8) : (tid - 7);   // -8..-1, 1..8
                int ny = y + off;
                if (ny >= 0 && ny < HH)
                    wait_flag(&g_flag[blk + off], base + (unsigned)(s + 1));
            }
            __syncthreads();
        } else {
            // ---- QKV projection (head = lane channel), packed float4 store -
            float wf[4];
            #pragma unroll
            for (int k = 0; k < 4; k++)
                wf[k] = __shfl_sync(0xffffffffu, wet, lb + k);
            const int pix = y * WW + col;
            float qv = __ldg(&ipb[c]);
            float kv = __ldg(&ipb[4 + c]);
            float vv = __ldg(&ipb[8 + c]);
            #pragma unroll
            for (int cc = 0; cc < CH; cc++) {
                qv = fmaf(__ldg(&ipw[c * CH + cc]),       wf[cc], qv);
                kv = fmaf(__ldg(&ipw[(4 + c) * CH + cc]), wf[cc], kv);
                vv = fmaf(__ldg(&ipw[(8 + c) * CH + cc]), wf[cc], vv);
            }
            __stcg(&g_qkv[batch][c][pix], make_float4(qv, kv * LOG2E, vv, 0.0f));
            __syncthreads();
            if (tid == 0) {
                __threadfence();
                atomicExch(&g_flag[blk], base + 4u);   // qkv ready
            }
        }
    }

    // ---- overlap: precompute the x-only epilogue terms for row y ----------
    if (tid < 64) {
        const int px = tid;
        float xin[CH][9];
        #pragma unroll
        for (int ci = 0; ci < CH; ci++)
            #pragma unroll
            for (int dy = 0; dy < 3; dy++)
                #pragma unroll
                for (int dx = 0; dx < 3; dx++) {
                    int yy = y + dy - 1, xx = px + dx - 1;
                    float v = 0.0f;
                    if (yy >= 0 && yy < HH && xx >= 0 && xx < WW)
                        v = __ldg(&x[((batch * CH + ci) * HH + yy) * WW + xx]);
                    xin[ci][dy * 3 + dx] = v;
                }
        #pragma unroll
        for (int j = 0; j < 2 * CH; j++) {
            float a = __ldg(&sc_b[j]);
            #pragma unroll
            for (int ci = 0; ci < CH; ci++)
                #pragma unroll
                for (int kk = 0; kk < 9; kk++)
                    a = fmaf(__ldg(&sc_w[(j * CH + ci) * 9 + kk]), xin[ci][kk], a);
            s_sp[j][px] = a;
        }
        #pragma unroll
        for (int cc = 0; cc < CH; cc++) s_xc[cc][px] = xin[cc][4];
    }

    // ===================== attention: phase B (node eval) ==================
    const int bh    = blk >> 4;      // 0..7
    const int chunk = blk & 15;      // 0..15
    const int b     = batch;         // == bh >> 2
    const int h     = bh & 3;

    // wait for all 64 blocks of this batch to publish qkv (parallel poll)
    if (tid < 64) wait_flag(&g_flag[b * 64 + tid], base + 4u);
    __syncthreads();

    // register-resident k,v for this thread's 16 tokens (no SMEM round trip)
    float k16[16], v16[16];
    float kmx = -3.4e38f, kmn = 3.4e38f, qmx = -3.4e38f, qmn = 3.4e38f;
    #pragma unroll
    for (int i = 0; i < 16; i++) {
        int j = i * NT + tid;
        float4 t4 = __ldcg(&g_qkv[b][h][j]);
        k16[i] = t4.y; v16[i] = t4.z;
        kmx = fmaxf(kmx, t4.y); kmn = fminf(kmn, t4.y);
        qmx = fmaxf(qmx, t4.x); qmn = fminf(qmn, t4.x);
        if (i == chunk) s_q[tid] = t4.x;
    }
    #pragma unroll
    for (int o = 16; o > 0; o >>= 1) {
        kmx = fmaxf(kmx, __shfl_xor_sync(0xffffffffu, kmx, o));
        kmn = fminf(kmn, __shfl_xor_sync(0xffffffffu, kmn, o));
        qmx = fmaxf(qmx, __shfl_xor_sync(0xffffffffu, qmx, o));
        qmn = fminf(qmn, __shfl_xor_sync(0xffffffffu, qmn, o));
    }
    const int wrp = tid >> 5;
    if (lane == 0) {
        s_red[wrp] = kmx; s_red[8 + wrp] = kmn;
        s_red[16 + wrp] = qmx; s_red[24 + wrp] = qmn;
    }
    __syncthreads();
    float ksmax = s_red[0], ksmin = s_red[8], qmax_ = s_red[16], qmin_ = s_red[24];
    #pragma unroll
    for (int i = 1; i < 8; i++) {
        ksmax = fmaxf(ksmax, s_red[i]);
        ksmin = fminf(ksmin, s_red[8 + i]);
        qmax_ = fmaxf(qmax_, s_red[16 + i]);
        qmin_ = fminf(qmin_, s_red[24 + i]);
    }

    const float dq = qmax_ - qmin_;
    const float dk = ksmax - ksmin;                 // log2 units
    const bool use_interp = (dq * dk <= 6.0f);      // guard for 16 nodes

    const float pad = 1e-4f * (fabsf(qmin_) + fabsf(qmax_)) + 1e-12f;
    const float a0 = qmin_ - pad, b0 = qmax_ + pad;
    const float cen = 0.5f * (a0 + b0), rad = 0.5f * (b0 - a0);
    if (tid < NNODE)
        s_nx[tid] = cen + rad * cosf((float)tid * (3.14159265358979323f / (NNODE - 1)));
    __syncthreads();

    if (use_interp) {
        // this block evaluates node == chunk, straight from registers
        const float qt = s_nx[chunk];
        const float m2 = (qt >= 0.0f) ? qt * ksmax : qt * ksmin;
        float num = 0.0f, den = 0.0f;
        #pragma unroll
        for (int i = 0; i < 16; i++) {
            float tt = fmaf(qt, k16[i], -m2);
            float e;
            asm("ex2.approx.f32 %0, %1;" : "=f"(e) : "f"(tt));
            den += e;
            num = fmaf(e, v16[i], num);
        }
        #pragma unroll
        for (int o = 16; o > 0; o >>= 1) {
            num += __shfl_xor_sync(0xffffffffu, num, o);
            den += __shfl_xor_sync(0xffffffffu, den, o);
        }
        if (lane == 0) { s_red[wrp] = num; s_red[8 + wrp] = den; }
        __syncthreads();
        if (tid == 0) {
            float N = 0.0f, D = 0.0f;
            #pragma unroll
            for (int w2 = 0; w2 < 8; w2++) { N += s_red[w2]; D += s_red[8 + w2]; }
            __stcg(&g_nodes[bh][chunk], N / D);
        }
    } else {
        // exact fallback: spill registers to SMEM, then full-LL per-query loop
        #pragma unroll
        for (int i = 0; i < 16; i++)
            s_kv[i * NT + tid] = make_float2(k16[i], v16[i]);
        __syncthreads();
    }
    __syncthreads();
    if (tid == 0) {
        __threadfence();
        atomicExch(&g_flag[blk], base + 5u);           // nodes ready
    }

    // ===================== attention: phase C (interpolate) ================
    if (tid < 16) wait_flag(&g_flag[bh * 16 + tid], base + 5u);
    __syncthreads();

    if (use_interp) {
        if (tid < NNODE) s_nR[tid] = __ldcg(&g_nodes[bh][tid]);
        __syncthreads();
        const float q = s_q[tid];
        float bn = 0.0f, bd = 0.0f;
        #pragma unroll
        for (int t2 = 0; t2 < NNODE; t2++) {
            float d = q - s_nx[t2];
            if (d == 0.0f) d = 1e-30f;
            float w = ((t2 == 0) || (t2 == NNODE - 1)) ? 0.5f : 1.0f;
            w = (t2 & 1) ? -w : w;
            float r = __fdividef(w, d);
            bn = fmaf(r, s_nR[t2], bn);
            bd += r;
        }
        __stcg(&g_attn[b][h][chunk * NT + tid], bn / bd);
    } else {
        const float qv = s_q[tid];
        const float m2 = (qv >= 0.0f) ? qv * ksmax : qv * ksmin;
        float num = 0.0f, den = 0.0f;
        #pragma unroll 8
        for (int j = 0; j < LL; j++) {
            float2 e2 = s_kv[j];
            float tt = fmaf(qv, e2.x, -m2);
            float e;
            asm("ex2.approx.f32 %0, %1;" : "=f"(e) : "f"(tt));
            den += e;
            num = fmaf(e, e2.y, num);
        }
        __stcg(&g_attn[b][h][chunk * NT + tid], num / den);
    }
    __syncthreads();
    if (tid == 0) {
        __threadfence();
        atomicExch(&g_flag[blk], base + 6u);           // attn ready
    }

    // =========================== epilogue: row y of this batch =============
    const int chunk_e = y >> 2;                        // (y*64)/256
    if (tid < 4)
        wait_flag(&g_flag[(batch * 4 + tid) * 16 + chunk_e], base + 6u);
    __syncthreads();

    if (tid < 64) {
        const int px  = tid;
        const int pix = y * WW + px;

        float o4[NHEADS];
        #pragma unroll
        for (int hh2 = 0; hh2 < NHEADS; hh2++) o4[hh2] = __ldcg(&g_attn[batch][hh2][pix]);
        float wet2[CH];
        #pragma unroll
        for (int cc = 0; cc < CH; cc++) {
            float a = __ldg(&opb[cc]);
            #pragma unroll
            for (int hh2 = 0; hh2 < NHEADS; hh2++)
                a = fmaf(__ldg(&opw[cc * CH + hh2]), o4[hh2], a);
            wet2[cc] = a;
        }

        #pragma unroll
        for (int cc = 0; cc < CH; cc++) {
            float a = __ldg(&ocb[cc]);
            #pragma unroll
            for (int j = 0; j < 2 * CH; j++)
                a = fmaf(__ldg(&ocw[cc * 12 + j]), s_sp[j][px], a);
            #pragma unroll
            for (int j = 0; j < CH; j++)
                a = fmaf(__ldg(&ocw[cc * 12 + 8 + j]), wet2[j], a);
            out[((batch * CH + cc) * HH + y) * WW + px] = 0.7f * s_xc[cc][px] + 0.3f * a;
        }
    }
}

// ---------------------------------------------------------------------------
extern "C" void kernel_launch(void* const* d_in, const int* in_sizes, int n_in,
                              void* d_out, int out_size)
{
    (void)in_sizes; (void)n_in; (void)out_size;
    const float* x      = (const float*)d_in[0];
    const float* refl_w = (const float*)d_in[1];
    const float* refl_d = (const float*)d_in[2];
    const float* sc_w   = (const float*)d_in[3];
    const float* sc_b   = (const float*)d_in[4];
    const float* fb_w   = (const float*)d_in[5];
    const float* fb_b   = (const float*)d_in[6];
    const float* d1_w   = (const float*)d_in[7];
    const float* d1_b   = (const float*)d_in[8];
    const float* d2_w   = (const float*)d_in[9];
    const float* d2_b   = (const float*)d_in[10];
    const float* ipw    = (const float*)d_in[11];
    const float* ipb    = (const float*)d_in[12];
    const float* opw    = (const float*)d_in[13];
    const float* opb    = (const float*)d_in[14];
    const float* oc_w   = (const float*)d_in[15];
    const float* oc_b   = (const float*)d_in[16];
    float* out = (float*)d_out;

    Params par;
    for (int r = 0; r < 4; r++)
        for (int c = 0; c < 7; c++) par.kern[r][c] = 0.0f;
    par.kern[0][3] = 1.0f;
    const int sizes[3] = {3, 5, 7};
    for (int ri = 0; ri < 3; ri++) {
        int ks = sizes[ri];
        double g[7], s = 0.0;
        for (int i = 0; i < ks; i++) {
            double xi = -2.0 + 4.0 * (double)i / (double)(ks - 1);
            g[i] = exp(-xi * xi);
            s += g[i];
        }
        int off = (7 - ks) / 2;
        for (int i = 0; i < ks; i++) par.kern[ri + 1][off + i] = (float)(g[i] / s);
    }
    for (int i = 0; i < 8; i++) par.pw[i] = (float)pow(0.8, (double)i);

    fused_kernel<<<NB, NT>>>(x, refl_w, refl_d, sc_w, sc_b, fb_w, fb_b,
                             d1_w, d1_b, d2_w, d2_b, ipw, ipb, opw, opb,
                             oc_w, oc_b, out, par);
}